// round 12
// baseline (speedup 1.0000x reference)
#include <cuda_runtime.h>

#define NATOMS 4096
#define DDESC  352
#define TILE   32
#define HID    256
#define NTILES 256          // 8192 slots / 32

// -------- scratch (device globals; no allocation allowed) --------
__device__ float4 g_xyz4[NATOMS];         // {x, y, z, (float)type}
__device__ float  g_descT[DDESC * 8192];  // transposed: [d][slot]; type0 slots 0.., type1 4096..
__device__ int    g_slot_atom[8192];
__device__ int    g_cnt[2];
__device__ int    g_work;
__device__ float  g_energy[NATOMS];

// Pack xyz + type into one float4 per atom; zero counters.
__global__ __launch_bounds__(256) void prep_kernel(
    const float* __restrict__ xyz, const int* __restrict__ types)
{
    int i = blockIdx.x * 256 + threadIdx.x;
    float4 p;
    p.x = xyz[3*i];
    p.y = xyz[3*i+1];
    p.z = xyz[3*i+2];
    p.w = (float)types[i];
    g_xyz4[i] = p;
    if (i < 2) g_cnt[i] = 0;
    if (i == 0) g_work = 0;
}

// Packed fp32x2 FMA (Blackwell; exact IEEE FMA per 32-bit lane).
__device__ __forceinline__ unsigned long long ffma2(
    unsigned long long a, unsigned long long b, unsigned long long c)
{
    unsigned long long d;
    asm("fma.rn.f32x2 %0, %1, %2, %3;" : "=l"(d) : "l"(a), "l"(b), "l"(c));
    return d;
}
__device__ __forceinline__ unsigned long long pack2(float w) {
    unsigned long long p;
    asm("mov.b64 %0, {%1, %1};" : "=l"(p) : "f"(w));
    return p;
}
__device__ __forceinline__ void unpack2(unsigned long long p, float& lo, float& hi) {
    asm("mov.b64 {%0, %1}, %2;" : "=f"(lo), "=f"(hi) : "l"(p));
}

// Inclusive block scan over 256 threads (shuffle-based). Operands may be
// packed 16+16-bit nonneg counts (each half total < 32768 -> no carry).
__device__ __forceinline__ int block_scan_incl(int v, int tid, int* wsum) {
    const int lane = tid & 31, w = tid >> 5;
    #pragma unroll
    for (int off = 1; off < 32; off <<= 1) {
        int u = __shfl_up_sync(0xffffffffu, v, off);
        if (lane >= off) v += u;
    }
    if (lane == 31) wsum[w] = v;
    __syncthreads();
    if (w == 0) {
        int s = (lane < 8) ? wsum[lane] : 0;
        #pragma unroll
        for (int off = 1; off < 8; off <<= 1) {
            int u = __shfl_up_sync(0xffffffffu, s, off);
            if (lane >= off) s += u;
        }
        if (lane < 8) wsum[lane] = s;
    }
    __syncthreads();
    if (w > 0) v += wsum[w - 1];
    __syncthreads();
    return v;
}

// =====================================================================
// Descriptor kernel: one block (256 thr) per atom. Dual-type radix
// select with PACKED u16 histograms (16 KB) and packed scans, then a
// FUSED dual 256-key bitonic sort (both types share barriers) on
// (distbits<<32)|idx -> JAX top_k stable order.
// __launch_bounds__(256,3): cap regs -> 3 blocks/SM.
// =====================================================================
__global__ __launch_bounds__(256, 3) void desc_kernel(
    const float* __restrict__ box)
{
    const int i   = blockIdx.x;
    const int tid = threadIdx.x;

    __shared__ int hist[4096];                // packed: t0 low16 | t1 high16 (16 KB)
    __shared__ int refine[256];               // packed
    __shared__ int wsum[8];
    __shared__ unsigned long long buf0[256];
    __shared__ unsigned long long buf1[256];
    __shared__ float s_sd[2][128];
    __shared__ int   s_idx[2][16];
    __shared__ float s_desc[DDESC];
    __shared__ float s_frame[9];
    __shared__ int s_bin[2], s_before[2], s_dig[2], s_count[2], s_slot;

    const float bx = box[0], by = box[1], bz = box[2];
    const float ibx = 1.0f / bx, iby = 1.0f / by, ibz = 1.0f / bz;
    const float4 pi = g_xyz4[i];
    const float xi = pi.x, yi = pi.y, zi = pi.z;

    // ---- distances for all 4096 atoms, kept in registers ----
    unsigned dbits[16];
    unsigned mask0 = 0, mask1 = 0;
    #pragma unroll
    for (int s = 0; s < 16; s++) {
        int j = s * 256 + tid;
        float4 p = __ldg(&g_xyz4[j]);
        float dx = xi - p.x + 1e-16f;
        float dy = yi - p.y + 1e-16f;
        float dz = zi - p.z + 1e-16f;
        dx -= bx * rintf(dx * ibx);
        dy -= by * rintf(dy * iby);
        dz -= bz * rintf(dz * ibz);
        float d = sqrtf(dx*dx + dy*dy + dz*dz);
        unsigned b = __float_as_uint(d);
        if (j == i) b = 0x7F800000u;
        dbits[s] = b;
        if (j != i) {
            if (p.w == 0.0f) mask0 |= 1u << s;
            else             mask1 |= 1u << s;
        }
    }

    // ---- zero packed histogram (int4) ----
    {
        int4 z = make_int4(0, 0, 0, 0);
        int4* h4 = (int4*)hist;
        #pragma unroll
        for (int k = 0; k < 4; k++) h4[k*256 + tid] = z;
    }
    if (tid < 2) s_count[tid] = 0;
    __syncthreads();

    // ---- one atomic fill pass into the packed hist ----
    #pragma unroll
    for (int s = 0; s < 16; s++) {
        if ((mask0 >> s) & 1u)      atomicAdd(&hist[dbits[s] >> 19], 1);
        else if ((mask1 >> s) & 1u) atomicAdd(&hist[dbits[s] >> 19], 1 << 16);
    }
    __syncthreads();

    // ---- locate rank-128 bin for both types with ONE packed scan ----
    int ls = 0;                                // packed group sum
    const int b0 = tid * 16;
    #pragma unroll
    for (int q = 0; q < 16; q++) ls += hist[b0 + q];   // halves never carry
    {
        int v = block_scan_incl(ls, tid, wsum);
        int ls0 = ls & 0xffff, ls1 = (unsigned)ls >> 16;
        int v0 = v & 0xffff,   v1 = (unsigned)v >> 16;
        int before0 = v0 - ls0, before1 = v1 - ls1;
        if (before0 < 128 && v0 >= 128) {
            int c = before0;
            #pragma unroll
            for (int q = 0; q < 16; q++) {
                int h = hist[b0 + q] & 0xffff;
                if (c + h >= 128) { s_bin[0] = b0 + q; s_before[0] = c; break; }
                c += h;
            }
        }
        if (before1 < 128 && v1 >= 128) {
            int c = before1;
            #pragma unroll
            for (int q = 0; q < 16; q++) {
                int h = (unsigned)hist[b0 + q] >> 16;
                if (c + h >= 128) { s_bin[1] = b0 + q; s_before[1] = c; break; }
                c += h;
            }
        }
    }
    refine[tid] = 0;
    __syncthreads();
    const int bin0 = s_bin[0], bin1 = s_bin[1];
    const int kk0 = 128 - s_before[0], kk1 = 128 - s_before[1];

    // ---- one refine fill pass (8-bit digit within selected bins) ----
    #pragma unroll
    for (int s = 0; s < 16; s++) {
        if (((mask0 >> s) & 1u) && (int)(dbits[s] >> 19) == bin0)
            atomicAdd(&refine[(dbits[s] >> 11) & 255], 1);
        else if (((mask1 >> s) & 1u) && (int)(dbits[s] >> 19) == bin1)
            atomicAdd(&refine[(dbits[s] >> 11) & 255], 1 << 16);
    }
    __syncthreads();
    {
        int r = refine[tid];
        int v = block_scan_incl(r, tid, wsum);
        int r0 = r & 0xffff, r1 = (unsigned)r >> 16;
        int v0 = v & 0xffff, v1 = (unsigned)v >> 16;
        if (v0 - r0 < kk0 && v0 >= kk0) s_dig[0] = tid;
        if (v1 - r1 < kk1 && v1 >= kk1) s_dig[1] = tid;
    }
    __syncthreads();
    const unsigned pivot0 = ((unsigned)bin0 << 8) | (unsigned)s_dig[0];
    const unsigned pivot1 = ((unsigned)bin1 << 8) | (unsigned)s_dig[1];

    // ---- one gather pass into both candidate buffers ----
    #pragma unroll
    for (int s = 0; s < 16; s++) {
        unsigned pre = dbits[s] >> 11;
        if (((mask0 >> s) & 1u) && pre <= pivot0) {
            int sl = atomicAdd(&s_count[0], 1);
            if (sl < 256)
                buf0[sl] = ((unsigned long long)dbits[s] << 32) | (unsigned)(s*256 + tid);
        } else if (((mask1 >> s) & 1u) && pre <= pivot1) {
            int sl = atomicAdd(&s_count[1], 1);
            if (sl < 256)
                buf1[sl] = ((unsigned long long)dbits[s] << 32) | (unsigned)(s*256 + tid);
        }
    }
    __syncthreads();
    const int n0 = (s_count[0] < 256) ? s_count[0] : 256;
    const int n1 = (s_count[1] < 256) ? s_count[1] : 256;
    unsigned long long k0 = (tid < n0) ? buf0[tid] : 0xFFFFFFFFFFFFFFFFull;
    unsigned long long k1 = (tid < n1) ? buf1[tid] : 0xFFFFFFFFFFFFFFFFull;
    __syncthreads();

    // ---- FUSED dual bitonic sort: both networks share barriers ----
    #pragma unroll
    for (int ksz = 2; ksz <= 256; ksz <<= 1) {
        #pragma unroll
        for (int jst = ksz >> 1; jst > 0; jst >>= 1) {
            const bool up = ((tid & ksz) == 0);
            unsigned long long o0, o1;
            if (jst >= 32) {
                buf0[tid] = k0; buf1[tid] = k1;
                __syncthreads();
                o0 = buf0[tid ^ jst]; o1 = buf1[tid ^ jst];
                __syncthreads();
            } else {
                o0 = __shfl_xor_sync(0xffffffffu, k0, jst);
                o1 = __shfl_xor_sync(0xffffffffu, k1, jst);
            }
            const bool keep_min = (((tid & jst) == 0) == up);
            if (keep_min ? (o0 < k0) : (o0 > k0)) k0 = o0;
            if (keep_min ? (o1 < k1) : (o1 > k1)) k1 = o1;
        }
    }
    if (tid < 128) {
        s_sd[0][tid] = __uint_as_float((unsigned)(k0 >> 32));
        s_sd[1][tid] = __uint_as_float((unsigned)(k1 >> 32));
        if (tid < 16) {
            s_idx[0][tid] = (int)(k0 & 0xFFFFFFFFu);
            s_idx[1][tid] = (int)(k1 & 0xFFFFFFFFu);
        }
    }
    __syncthreads();

    // ---- inverse-distance descriptor blocks ----
    {
        int t = tid >> 7, r = tid & 127;
        s_desc[tid] = 1.0f / (s_sd[t][r] + 1e-16f);
    }

    // ---- local frame (thread 0; trivial) ----
    if (tid == 0) {
        float cd[4]; int ci[4];
        cd[0]=s_sd[0][0]; ci[0]=s_idx[0][0];
        cd[1]=s_sd[0][1]; ci[1]=s_idx[0][1];
        cd[2]=s_sd[1][0]; ci[2]=s_idx[1][0];
        cd[3]=s_sd[1][1]; ci[3]=s_idx[1][1];
        int a0 = 0;
        for (int q = 1; q < 4; q++) if (cd[q] < cd[a0]) a0 = q;   // stable min
        int a1 = -1;
        for (int q = 0; q < 4; q++) if (q != a0 && (a1 < 0 || cd[q] < cd[a1])) a1 = q;

        float r0[3], r1[3];
        for (int p = 0; p < 2; p++) {
            int sel = p ? a1 : a0;
            float4 pj = g_xyz4[ci[sel]];
            float dm0 = xi - pj.x + 1e-16f;
            float dm1 = yi - pj.y + 1e-16f;
            float dm2 = zi - pj.z + 1e-16f;
            dm0 -= bx * rintf(dm0 * ibx);
            dm1 -= by * rintf(dm1 * iby);
            dm2 -= bz * rintf(dm2 * ibz);
            float den = cd[sel] + 1e-16f;
            float* r = p ? r1 : r0;
            r[0] = dm0/den; r[1] = dm1/den; r[2] = dm2/den;
        }
        float dot = r0[0]*r1[0] + r0[1]*r1[1] + r0[2]*r1[2];
        float v2[3] = { r1[0]-dot*r0[0], r1[1]-dot*r0[1], r1[2]-dot*r0[2] };
        float n2 = sqrtf(v2[0]*v2[0] + v2[1]*v2[1] + v2[2]*v2[2]);
        v2[0] /= n2; v2[1] /= n2; v2[2] /= n2;
        float v3[3] = { r0[1]*r1[2]-r0[2]*r1[1],
                        r0[2]*r1[0]-r0[0]*r1[2],
                        r0[0]*r1[1]-r0[1]*r1[0] };
        float n3 = sqrtf(v3[0]*v3[0] + v3[1]*v3[1] + v3[2]*v3[2]);
        v3[0] /= n3; v3[1] /= n3; v3[2] /= n3;
        s_frame[0]=r0[0]; s_frame[1]=r0[1]; s_frame[2]=r0[2];
        s_frame[3]=v2[0]; s_frame[4]=v2[1]; s_frame[5]=v2[2];
        s_frame[6]=v3[0]; s_frame[7]=v3[1]; s_frame[8]=v3[2];

        int ti = (pi.w != 0.0f) ? 1 : 0;
        int sl = 4096*ti + atomicAdd(&g_cnt[ti], 1);
        g_slot_atom[sl] = i;
        s_slot = sl;
    }
    __syncthreads();

    // ---- rotated angular part: 32 neighbors x 3 components ----
    if (tid < 32) {
        int t = tid >> 4, r = tid & 15;
        float4 pj = g_xyz4[s_idx[t][r]];
        float d = s_sd[t][r];
        float dm0 = xi - pj.x + 1e-16f;
        float dm1 = yi - pj.y + 1e-16f;
        float dm2 = zi - pj.z + 1e-16f;
        dm0 -= bx * rintf(dm0 * ibx);
        dm1 -= by * rintf(dm1 * iby);
        dm2 -= bz * rintf(dm2 * ibz);
        float den = d + 1e-16f;
        float anx = dm0/den, any = dm1/den, anz = dm2/den;
        #pragma unroll
        for (int rr = 0; rr < 3; rr++) {
            float val = s_frame[3*rr+0]*anx + s_frame[3*rr+1]*any + s_frame[3*rr+2]*anz;
            s_desc[256 + 3*tid + rr] = val / den;
        }
    }
    __syncthreads();

    // ---- write transposed descriptor ----
    {
        float* dst = g_descT + s_slot + (size_t)tid * 8192;
        for (int c = tid; c < DDESC; c += 256, dst += 256 * 8192)
            *dst = s_desc[c];
    }
}

// =====================================================================
// MLP kernel: persistent work-stealing. 296 blocks (2/SM) pull 32-atom
// tiles from a global counter -> perfect SM balance. FFMA2 + LDS.128.
// =====================================================================
__device__ __forceinline__ void mlp_layer(
    const float* __restrict__ W, float bb, int din,
    float* __restrict__ sA, int tid)
{
    unsigned long long acc2[TILE/2];
    #pragma unroll
    for (int k = 0; k < TILE/2; k++) acc2[k] = 0ull;

    #pragma unroll 4
    for (int d = 0; d < din; d++) {
        const unsigned long long w2 = pack2(__ldg(&W[d*HID]));
        const ulonglong2* r2 = (const ulonglong2*)(sA + d*TILE);
        #pragma unroll
        for (int q = 0; q < TILE/4; q++) {
            ulonglong2 r = r2[q];                      // LDS.128 broadcast
            acc2[2*q+0] = ffma2(w2, r.x, acc2[2*q+0]);
            acc2[2*q+1] = ffma2(w2, r.y, acc2[2*q+1]);
        }
    }
    __syncthreads();
    float4* out4 = (float4*)(sA + tid*TILE);
    #pragma unroll
    for (int q = 0; q < TILE/4; q++) {
        float a0, a1, a2, a3;
        unpack2(acc2[2*q+0], a0, a1);
        unpack2(acc2[2*q+1], a2, a3);
        float4 o;
        o.x = tanhf(a0 + bb);
        o.y = tanhf(a1 + bb);
        o.z = tanhf(a2 + bb);
        o.w = tanhf(a3 + bb);
        out4[q] = o;
    }
    __syncthreads();
}

__global__ __launch_bounds__(256) void mlp_kernel(
    const float* __restrict__ w1, const float* __restrict__ b1,
    const float* __restrict__ w2, const float* __restrict__ b2,
    const float* __restrict__ w3, const float* __restrict__ b3,
    const float* __restrict__ w4, const float* __restrict__ b4)
{
    __shared__ float sA[DDESC * TILE];        // 45056 B
    __shared__ float s_red[8 * TILE];
    __shared__ int s_tile;

    const int tid = threadIdx.x;

    for (;;) {
        if (tid == 0) s_tile = atomicAdd(&g_work, 1);
        __syncthreads();
        const int tile = s_tile;
        if (tile >= NTILES) break;            // uniform exit

        const int t    = tile >> 7;
        const int base = (tile & 127) * TILE;
        const int cnt  = g_cnt[t];
        if (base < cnt) {                     // block-uniform condition
            const int slot0 = 4096*t + base;

            for (int e = tid; e < DDESC*TILE; e += 256) {
                int d = e >> 5, a = e & 31;
                sA[e] = g_descT[d*8192 + slot0 + a];
            }
            __syncthreads();

            mlp_layer(w1 + t*DDESC*HID + tid, b1[t*HID + tid], DDESC, sA, tid);
            mlp_layer(w2 + t*HID*HID  + tid, b2[t*HID + tid], HID,   sA, tid);
            mlp_layer(w3 + t*HID*HID  + tid, b3[t*HID + tid], HID,   sA, tid);

            // layer 4: 256 -> 1, block reduction per atom
            float w4v = w4[t*HID + tid];
            float pv[TILE];
            #pragma unroll
            for (int a = 0; a < TILE; a++) pv[a] = w4v * sA[tid*TILE + a];
            #pragma unroll
            for (int off = 16; off; off >>= 1) {
                #pragma unroll
                for (int a = 0; a < TILE; a++)
                    pv[a] += __shfl_down_sync(0xffffffffu, pv[a], off);
            }
            if ((tid & 31) == 0) {
                #pragma unroll
                for (int a = 0; a < TILE; a++) s_red[(tid >> 5)*TILE + a] = pv[a];
            }
            __syncthreads();
            if (tid < TILE) {
                float s = 0.f;
                #pragma unroll
                for (int w = 0; w < 8; w++) s += s_red[w*TILE + tid];
                if (base + tid < cnt)
                    g_energy[g_slot_atom[slot0 + tid]] = s + b4[t];
            }
        }
        __syncthreads();                      // s_tile safe to overwrite
    }
}

// =====================================================================
// Deterministic fixed-order final reduction
// =====================================================================
__global__ void reduce_kernel(float* __restrict__ out) {
    __shared__ float sh[1024];
    int tid = threadIdx.x;
    float s = g_energy[tid] + g_energy[tid+1024] +
              g_energy[tid+2048] + g_energy[tid+3072];
    sh[tid] = s;
    __syncthreads();
    for (int off = 512; off; off >>= 1) {
        if (tid < off) sh[tid] += sh[tid + off];
        __syncthreads();
    }
    if (tid == 0) out[0] = sh[0];
}

// =====================================================================
extern "C" void kernel_launch(void* const* d_in, const int* in_sizes, int n_in,
                              void* d_out, int out_size)
{
    const float* xyz   = (const float*)d_in[0];
    const float* box   = (const float*)d_in[1];
    const int*   types = (const int*)d_in[2];
    const float* w1 = (const float*)d_in[3];
    const float* b1 = (const float*)d_in[4];
    const float* w2 = (const float*)d_in[5];
    const float* b2 = (const float*)d_in[6];
    const float* w3 = (const float*)d_in[7];
    const float* b3 = (const float*)d_in[8];
    const float* w4 = (const float*)d_in[9];
    const float* b4 = (const float*)d_in[10];

    prep_kernel<<<NATOMS/256, 256>>>(xyz, types);
    desc_kernel<<<NATOMS, 256>>>(box);
    mlp_kernel<<<296, 256>>>(w1, b1, w2, b2, w3, b3, w4, b4);
    reduce_kernel<<<1, 1024>>>((float*)d_out);
}

// round 13
// speedup vs baseline: 1.0999x; 1.0999x over previous
#include <cuda_runtime.h>

#define NATOMS 4096
#define DDESC  352
#define TILE   32
#define HID    256
#define NTILES 256          // 8192 slots / 32

// -------- scratch (device globals; no allocation allowed) --------
__device__ float4 g_xyz4[NATOMS];         // {x, y, z, (float)type}
__device__ float  g_descT[DDESC * 8192];  // transposed: [d][slot]; type0 slots 0.., type1 4096..
__device__ int    g_slot_atom[8192];
__device__ int    g_cnt[2];
__device__ int    g_work;
__device__ float  g_energy[NATOMS];

// Pack xyz + type into one float4 per atom; zero counters.
__global__ __launch_bounds__(256) void prep_kernel(
    const float* __restrict__ xyz, const int* __restrict__ types)
{
    int i = blockIdx.x * 256 + threadIdx.x;
    float4 p;
    p.x = xyz[3*i];
    p.y = xyz[3*i+1];
    p.z = xyz[3*i+2];
    p.w = (float)types[i];
    g_xyz4[i] = p;
    if (i < 2) g_cnt[i] = 0;
    if (i == 0) g_work = 0;
}

// Packed fp32x2 FMA (Blackwell; exact IEEE FMA per 32-bit lane).
__device__ __forceinline__ unsigned long long ffma2(
    unsigned long long a, unsigned long long b, unsigned long long c)
{
    unsigned long long d;
    asm("fma.rn.f32x2 %0, %1, %2, %3;" : "=l"(d) : "l"(a), "l"(b), "l"(c));
    return d;
}
__device__ __forceinline__ unsigned long long pack2(float w) {
    unsigned long long p;
    asm("mov.b64 %0, {%1, %1};" : "=l"(p) : "f"(w));
    return p;
}
__device__ __forceinline__ void unpack2(unsigned long long p, float& lo, float& hi) {
    asm("mov.b64 {%0, %1}, %2;" : "=f"(lo), "=f"(hi) : "l"(p));
}

// =====================================================================
// Descriptor kernel: one block (256 thr) per atom. ATOMIC-FREE pivot
// search (cube-root interpolated bisection on float bits; packed 16+16
// per-type counts; one block-reduce per iteration), then a fused dual
// 256-key bitonic sort on (distbits<<32)|idx -> JAX top_k stable order.
// =====================================================================
__global__ __launch_bounds__(256, 3) void desc_kernel(
    const float* __restrict__ box)
{
    const int i   = blockIdx.x;
    const int tid = threadIdx.x;

    __shared__ int wsum[8];
    __shared__ unsigned long long buf0[256];
    __shared__ unsigned long long buf1[256];
    __shared__ float s_sd[2][128];
    __shared__ int   s_idx[2][16];
    __shared__ float s_desc[DDESC];
    __shared__ float s_frame[9];
    __shared__ unsigned s_lo[2], s_hi[2], s_mid[2], s_piv[2];
    __shared__ int s_dv[2], s_done, s_count[2], s_slot;

    const float bx = box[0], by = box[1], bz = box[2];
    const float ibx = 1.0f / bx, iby = 1.0f / by, ibz = 1.0f / bz;
    const float4 pi = g_xyz4[i];
    const float xi = pi.x, yi = pi.y, zi = pi.z;

    // ---- distances for all 4096 atoms, kept in registers ----
    unsigned dbits[16];
    unsigned mask0 = 0, mask1 = 0;
    #pragma unroll
    for (int s = 0; s < 16; s++) {
        int j = s * 256 + tid;
        float4 p = __ldg(&g_xyz4[j]);
        float dx = xi - p.x + 1e-16f;
        float dy = yi - p.y + 1e-16f;
        float dz = zi - p.z + 1e-16f;
        dx -= bx * rintf(dx * ibx);
        dy -= by * rintf(dy * iby);
        dz -= bz * rintf(dz * ibz);
        float d = sqrtf(dx*dx + dy*dy + dz*dz);
        unsigned b = __float_as_uint(d);
        if (j == i) b = 0x7F800000u;
        dbits[s] = b;
        if (j != i) {
            if (p.w == 0.0f) mask0 |= 1u << s;
            else             mask1 |= 1u << s;
        }
    }

    // ---- pivot search: find piv_t with count(dbits<=piv_t) in [128,256] ----
    if (tid == 0) {
        s_lo[0] = s_lo[1] = 0u;
        s_hi[0] = s_hi[1] = __float_as_uint(35.0f);   // > max PBC distance 34.65
        s_mid[0] = s_mid[1] = __float_as_uint(10.5f); // expected count ~155
        s_dv[0] = s_dv[1] = 0; s_done = 0;
        s_count[0] = s_count[1] = 0;
    }
    __syncthreads();

    for (int it = 0; it < 32; ++it) {
        const unsigned m0 = s_mid[0], m1 = s_mid[1];
        int cnt = 0;                          // packed c0 | c1<<16 (<=2048 each)
        #pragma unroll
        for (int s = 0; s < 16; s++) {
            cnt += (int)(((mask0 >> s) & 1u) && (dbits[s] <= m0));
            cnt += ((int)(((mask1 >> s) & 1u) && (dbits[s] <= m1))) << 16;
        }
        #pragma unroll
        for (int off = 16; off; off >>= 1)
            cnt += __shfl_down_sync(0xffffffffu, cnt, off);
        if ((tid & 31) == 0) wsum[tid >> 5] = cnt;
        __syncthreads();
        if (tid == 0) {
            int tot = 0;
            #pragma unroll
            for (int w = 0; w < 8; w++) tot += wsum[w];
            int c[2] = { tot & 0xffff, (int)((unsigned)tot >> 16) };
            int done = 1;
            for (int t = 0; t < 2; t++) {
                if (!s_dv[t]) {
                    unsigned mid = s_mid[t];
                    if (c[t] >= 128 && c[t] <= 256) { s_piv[t] = mid; s_dv[t] = 1; }
                    else {
                        unsigned lo = s_lo[t], hi = s_hi[t];
                        if (c[t] < 128) lo = mid; else hi = mid;
                        float rm = __uint_as_float(mid);
                        int cc = c[t] < 4 ? 4 : c[t];
                        float rn = rm * cbrtf(180.0f / (float)cc);
                        unsigned nm = __float_as_uint(rn);
                        if (nm <= lo || nm >= hi) nm = lo + ((hi - lo) >> 1);
                        s_lo[t] = lo; s_hi[t] = hi; s_mid[t] = nm;
                    }
                }
                done &= s_dv[t];
            }
            s_done = done;
        }
        __syncthreads();
        if (s_done) break;
    }
    if (tid == 0) {                           // fallback (prob ~0)
        if (!s_dv[0]) s_piv[0] = s_hi[0];
        if (!s_dv[1]) s_piv[1] = s_hi[1];
    }
    __syncthreads();
    const unsigned piv0 = s_piv[0], piv1 = s_piv[1];

    // ---- one gather pass into both candidate buffers (<=256 each) ----
    #pragma unroll
    for (int s = 0; s < 16; s++) {
        if (((mask0 >> s) & 1u) && dbits[s] <= piv0) {
            int sl = atomicAdd(&s_count[0], 1);
            if (sl < 256)
                buf0[sl] = ((unsigned long long)dbits[s] << 32) | (unsigned)(s*256 + tid);
        } else if (((mask1 >> s) & 1u) && dbits[s] <= piv1) {
            int sl = atomicAdd(&s_count[1], 1);
            if (sl < 256)
                buf1[sl] = ((unsigned long long)dbits[s] << 32) | (unsigned)(s*256 + tid);
        }
    }
    __syncthreads();
    const int n0 = (s_count[0] < 256) ? s_count[0] : 256;
    const int n1 = (s_count[1] < 256) ? s_count[1] : 256;
    unsigned long long k0 = (tid < n0) ? buf0[tid] : 0xFFFFFFFFFFFFFFFFull;
    unsigned long long k1 = (tid < n1) ? buf1[tid] : 0xFFFFFFFFFFFFFFFFull;
    __syncthreads();

    // ---- fused dual bitonic sort: both networks share barriers ----
    #pragma unroll
    for (int ksz = 2; ksz <= 256; ksz <<= 1) {
        #pragma unroll
        for (int jst = ksz >> 1; jst > 0; jst >>= 1) {
            const bool up = ((tid & ksz) == 0);
            unsigned long long o0, o1;
            if (jst >= 32) {
                buf0[tid] = k0; buf1[tid] = k1;
                __syncthreads();
                o0 = buf0[tid ^ jst]; o1 = buf1[tid ^ jst];
                __syncthreads();
            } else {
                o0 = __shfl_xor_sync(0xffffffffu, k0, jst);
                o1 = __shfl_xor_sync(0xffffffffu, k1, jst);
            }
            const bool keep_min = (((tid & jst) == 0) == up);
            if (keep_min ? (o0 < k0) : (o0 > k0)) k0 = o0;
            if (keep_min ? (o1 < k1) : (o1 > k1)) k1 = o1;
        }
    }
    if (tid < 128) {
        s_sd[0][tid] = __uint_as_float((unsigned)(k0 >> 32));
        s_sd[1][tid] = __uint_as_float((unsigned)(k1 >> 32));
        if (tid < 16) {
            s_idx[0][tid] = (int)(k0 & 0xFFFFFFFFu);
            s_idx[1][tid] = (int)(k1 & 0xFFFFFFFFu);
        }
    }
    __syncthreads();

    // ---- inverse-distance descriptor blocks ----
    {
        int t = tid >> 7, r = tid & 127;
        s_desc[tid] = 1.0f / (s_sd[t][r] + 1e-16f);
    }

    // ---- local frame (thread 0; trivial) ----
    if (tid == 0) {
        float cd[4]; int ci[4];
        cd[0]=s_sd[0][0]; ci[0]=s_idx[0][0];
        cd[1]=s_sd[0][1]; ci[1]=s_idx[0][1];
        cd[2]=s_sd[1][0]; ci[2]=s_idx[1][0];
        cd[3]=s_sd[1][1]; ci[3]=s_idx[1][1];
        int a0 = 0;
        for (int q = 1; q < 4; q++) if (cd[q] < cd[a0]) a0 = q;   // stable min
        int a1 = -1;
        for (int q = 0; q < 4; q++) if (q != a0 && (a1 < 0 || cd[q] < cd[a1])) a1 = q;

        float r0[3], r1[3];
        for (int p = 0; p < 2; p++) {
            int sel = p ? a1 : a0;
            float4 pj = g_xyz4[ci[sel]];
            float dm0 = xi - pj.x + 1e-16f;
            float dm1 = yi - pj.y + 1e-16f;
            float dm2 = zi - pj.z + 1e-16f;
            dm0 -= bx * rintf(dm0 * ibx);
            dm1 -= by * rintf(dm1 * iby);
            dm2 -= bz * rintf(dm2 * ibz);
            float den = cd[sel] + 1e-16f;
            float* r = p ? r1 : r0;
            r[0] = dm0/den; r[1] = dm1/den; r[2] = dm2/den;
        }
        float dot = r0[0]*r1[0] + r0[1]*r1[1] + r0[2]*r1[2];
        float v2[3] = { r1[0]-dot*r0[0], r1[1]-dot*r0[1], r1[2]-dot*r0[2] };
        float n2 = sqrtf(v2[0]*v2[0] + v2[1]*v2[1] + v2[2]*v2[2]);
        v2[0] /= n2; v2[1] /= n2; v2[2] /= n2;
        float v3[3] = { r0[1]*r1[2]-r0[2]*r1[1],
                        r0[2]*r1[0]-r0[0]*r1[2],
                        r0[0]*r1[1]-r0[1]*r1[0] };
        float n3 = sqrtf(v3[0]*v3[0] + v3[1]*v3[1] + v3[2]*v3[2]);
        v3[0] /= n3; v3[1] /= n3; v3[2] /= n3;
        s_frame[0]=r0[0]; s_frame[1]=r0[1]; s_frame[2]=r0[2];
        s_frame[3]=v2[0]; s_frame[4]=v2[1]; s_frame[5]=v2[2];
        s_frame[6]=v3[0]; s_frame[7]=v3[1]; s_frame[8]=v3[2];

        int ti = (pi.w != 0.0f) ? 1 : 0;
        int sl = 4096*ti + atomicAdd(&g_cnt[ti], 1);
        g_slot_atom[sl] = i;
        s_slot = sl;
    }
    __syncthreads();

    // ---- rotated angular part: 32 neighbors x 3 components ----
    if (tid < 32) {
        int t = tid >> 4, r = tid & 15;
        float4 pj = g_xyz4[s_idx[t][r]];
        float d = s_sd[t][r];
        float dm0 = xi - pj.x + 1e-16f;
        float dm1 = yi - pj.y + 1e-16f;
        float dm2 = zi - pj.z + 1e-16f;
        dm0 -= bx * rintf(dm0 * ibx);
        dm1 -= by * rintf(dm1 * iby);
        dm2 -= bz * rintf(dm2 * ibz);
        float den = d + 1e-16f;
        float anx = dm0/den, any = dm1/den, anz = dm2/den;
        #pragma unroll
        for (int rr = 0; rr < 3; rr++) {
            float val = s_frame[3*rr+0]*anx + s_frame[3*rr+1]*any + s_frame[3*rr+2]*anz;
            s_desc[256 + 3*tid + rr] = val / den;
        }
    }
    __syncthreads();

    // ---- write transposed descriptor ----
    {
        float* dst = g_descT + s_slot + (size_t)tid * 8192;
        for (int c = tid; c < DDESC; c += 256, dst += 256 * 8192)
            *dst = s_desc[c];
    }
}

// =====================================================================
// MLP kernel: persistent work-stealing. 296 blocks (2/SM) pull 32-atom
// tiles from a global counter -> perfect SM balance. FFMA2 + LDS.128.
// =====================================================================
__device__ __forceinline__ void mlp_layer(
    const float* __restrict__ W, float bb, int din,
    float* __restrict__ sA, int tid)
{
    unsigned long long acc2[TILE/2];
    #pragma unroll
    for (int k = 0; k < TILE/2; k++) acc2[k] = 0ull;

    #pragma unroll 4
    for (int d = 0; d < din; d++) {
        const unsigned long long w2 = pack2(__ldg(&W[d*HID]));
        const ulonglong2* r2 = (const ulonglong2*)(sA + d*TILE);
        #pragma unroll
        for (int q = 0; q < TILE/4; q++) {
            ulonglong2 r = r2[q];                      // LDS.128 broadcast
            acc2[2*q+0] = ffma2(w2, r.x, acc2[2*q+0]);
            acc2[2*q+1] = ffma2(w2, r.y, acc2[2*q+1]);
        }
    }
    __syncthreads();
    float4* out4 = (float4*)(sA + tid*TILE);
    #pragma unroll
    for (int q = 0; q < TILE/4; q++) {
        float a0, a1, a2, a3;
        unpack2(acc2[2*q+0], a0, a1);
        unpack2(acc2[2*q+1], a2, a3);
        float4 o;
        o.x = tanhf(a0 + bb);
        o.y = tanhf(a1 + bb);
        o.z = tanhf(a2 + bb);
        o.w = tanhf(a3 + bb);
        out4[q] = o;
    }
    __syncthreads();
}

__global__ __launch_bounds__(256) void mlp_kernel(
    const float* __restrict__ w1, const float* __restrict__ b1,
    const float* __restrict__ w2, const float* __restrict__ b2,
    const float* __restrict__ w3, const float* __restrict__ b3,
    const float* __restrict__ w4, const float* __restrict__ b4)
{
    __shared__ float sA[DDESC * TILE];        // 45056 B
    __shared__ float s_red[8 * TILE];
    __shared__ int s_tile;

    const int tid = threadIdx.x;

    for (;;) {
        if (tid == 0) s_tile = atomicAdd(&g_work, 1);
        __syncthreads();
        const int tile = s_tile;
        if (tile >= NTILES) break;            // uniform exit

        const int t    = tile >> 7;
        const int base = (tile & 127) * TILE;
        const int cnt  = g_cnt[t];
        if (base < cnt) {                     // block-uniform condition
            const int slot0 = 4096*t + base;

            for (int e = tid; e < DDESC*TILE; e += 256) {
                int d = e >> 5, a = e & 31;
                sA[e] = g_descT[d*8192 + slot0 + a];
            }
            __syncthreads();

            mlp_layer(w1 + t*DDESC*HID + tid, b1[t*HID + tid], DDESC, sA, tid);
            mlp_layer(w2 + t*HID*HID  + tid, b2[t*HID + tid], HID,   sA, tid);
            mlp_layer(w3 + t*HID*HID  + tid, b3[t*HID + tid], HID,   sA, tid);

            // layer 4: 256 -> 1, block reduction per atom
            float w4v = w4[t*HID + tid];
            float pv[TILE];
            #pragma unroll
            for (int a = 0; a < TILE; a++) pv[a] = w4v * sA[tid*TILE + a];
            #pragma unroll
            for (int off = 16; off; off >>= 1) {
                #pragma unroll
                for (int a = 0; a < TILE; a++)
                    pv[a] += __shfl_down_sync(0xffffffffu, pv[a], off);
            }
            if ((tid & 31) == 0) {
                #pragma unroll
                for (int a = 0; a < TILE; a++) s_red[(tid >> 5)*TILE + a] = pv[a];
            }
            __syncthreads();
            if (tid < TILE) {
                float s = 0.f;
                #pragma unroll
                for (int w = 0; w < 8; w++) s += s_red[w*TILE + tid];
                if (base + tid < cnt)
                    g_energy[g_slot_atom[slot0 + tid]] = s + b4[t];
            }
        }
        __syncthreads();                      // s_tile safe to overwrite
    }
}

// =====================================================================
// Deterministic fixed-order final reduction
// =====================================================================
__global__ void reduce_kernel(float* __restrict__ out) {
    __shared__ float sh[1024];
    int tid = threadIdx.x;
    float s = g_energy[tid] + g_energy[tid+1024] +
              g_energy[tid+2048] + g_energy[tid+3072];
    sh[tid] = s;
    __syncthreads();
    for (int off = 512; off; off >>= 1) {
        if (tid < off) sh[tid] += sh[tid + off];
        __syncthreads();
    }
    if (tid == 0) out[0] = sh[0];
}

// =====================================================================
extern "C" void kernel_launch(void* const* d_in, const int* in_sizes, int n_in,
                              void* d_out, int out_size)
{
    const float* xyz   = (const float*)d_in[0];
    const float* box   = (const float*)d_in[1];
    const int*   types = (const int*)d_in[2];
    const float* w1 = (const float*)d_in[3];
    const float* b1 = (const float*)d_in[4];
    const float* w2 = (const float*)d_in[5];
    const float* b2 = (const float*)d_in[6];
    const float* w3 = (const float*)d_in[7];
    const float* b3 = (const float*)d_in[8];
    const float* w4 = (const float*)d_in[9];
    const float* b4 = (const float*)d_in[10];

    prep_kernel<<<NATOMS/256, 256>>>(xyz, types);
    desc_kernel<<<NATOMS, 256>>>(box);
    mlp_kernel<<<296, 256>>>(w1, b1, w2, b2, w3, b3, w4, b4);
    reduce_kernel<<<1, 1024>>>((float*)d_out);
}